// round 11
// baseline (speedup 1.0000x reference)
#include <cuda_runtime.h>

#define B_  2
#define C_  272
#define H_  128
#define W_  128
#define G_  17
#define CG_ 16
#define HW_ (H_*W_)
#define PH_ 130
#define PHW_ (PH_*PH_)   // padded plane 130x130

// ---------------- scratch (device globals; no allocation) ----------------
__device__ __align__(16) float g_xT[B_*G_*PHW_*CG_];    // (b,g, padpos, c16), zero halo
__device__ __align__(16) float g_conv[B_*C_*HW_];       // (B,C,H,W)
__device__ float g_sum[C_];
__device__ float g_sumsq[C_];
__device__ float g_mean[C_];
__device__ float g_istd[C_];

// ---------------- packed f32x2 helpers ----------------
__device__ __forceinline__ unsigned long long pack2(float lo, float hi) {
    unsigned long long r;
    asm("mov.b64 %0, {%1,%2};" : "=l"(r) : "f"(lo), "f"(hi));
    return r;
}
__device__ __forceinline__ float2 unpack2(unsigned long long v) {
    float2 r;
    asm("mov.b64 {%0,%1}, %2;" : "=f"(r.x), "=f"(r.y) : "l"(v));
    return r;
}
__device__ __forceinline__ void fma2(unsigned long long& d,
                                     unsigned long long a, unsigned long long b) {
    asm("fma.rn.f32x2 %0, %1, %2, %0;" : "+l"(d) : "l"(a), "l"(b));
}

// ---------------- K-1: zero the halo of g_xT + stats accumulators ----------
__global__ void k_zero() {
    int t = blockIdx.x * blockDim.x + threadIdx.x;
    if (t < C_) { g_sum[t] = 0.f; g_sumsq[t] = 0.f; }
    const int total = B_*G_ * 516 * 4;   // 516 halo cells per plane, 4 quads
    if (t >= total) return;
    int c4 = t & 3, cell = t >> 2;
    int bg = cell / 516, p = cell - bg * 516;
    int y, x;
    if (p < 130)      { y = 0;   x = p; }
    else if (p < 260) { y = 129; x = p - 130; }
    else { int r = p - 260; y = 1 + (r >> 1); x = (r & 1) * 129; }
    float4* dst = reinterpret_cast<float4*>(g_xT)
                + ((size_t)bg * PHW_ + y * PH_ + x) * 4 + c4;
    *dst = make_float4(0.f, 0.f, 0.f, 0.f);
}

// ---------------- K0: transpose x (B,C,H,W) -> padded (b,g,pady,padx,c16) ----
__global__ void __launch_bounds__(256) k_transpose(const float* __restrict__ x) {
    __shared__ float sh[16 * 257];
    const int bg   = blockIdx.y;
    const int base = blockIdx.x * 256;       // 256 positions = 2 rows
    const float* src = x + (size_t)bg * 16 * HW_ + base;
    #pragma unroll
    for (int c = 0; c < 16; c++)
        sh[c * 257 + threadIdx.x] = src[(size_t)c * HW_ + threadIdx.x];
    __syncthreads();
    float4* dst = reinterpret_cast<float4*>(g_xT);
    #pragma unroll
    for (int it = 0; it < 4; it++) {
        int idx = it * 256 + threadIdx.x;
        int p = idx >> 2, q = idx & 3;
        int pos = base + p;
        int h = pos >> 7, w = pos & (W_ - 1);
        float4 v;
        v.x = sh[(4*q + 0) * 257 + p];
        v.y = sh[(4*q + 1) * 257 + p];
        v.z = sh[(4*q + 2) * 257 + p];
        v.w = sh[(4*q + 3) * 257 + p];
        dst[((size_t)bg * PHW_ + (h + 1) * PH_ + (w + 1)) * 4 + q] = v;
    }
}

// ---------------- bilinear gather (R6 exact, packed dataflow) ----------------
__device__ __forceinline__ void bilin_gather(const ulonglong2* __restrict__ xb,
                                             float2 off, int h, int w,
                                             int ky, int kx,
                                             unsigned long long& s0,
                                             unsigned long long& s1) {
    float py = (float)(h + ky) + off.x;
    float px = (float)(w + kx) + off.y;
    float y0f = floorf(py), x0f = floorf(px);
    float wy = py - y0f, wx = px - x0f;
    int y0 = (int)y0f, x0 = (int)x0f;
    int y1 = y0 + 1, x1 = x0 + 1;
    bool vy0 = (unsigned)y0 < H_, vy1 = (unsigned)y1 < H_;
    bool vx0 = (unsigned)x0 < W_, vx1 = (unsigned)x1 < W_;
    int y0c = min(max(y0, 0), H_-1), y1c = min(max(y1, 0), H_-1);
    int x0c = min(max(x0, 0), W_-1), x1c = min(max(x1, 0), W_-1);
    float w00 = (vy0 && vx0) ? (1.f - wy) * (1.f - wx) : 0.f;
    float w01 = (vy0 && vx1) ? (1.f - wy) * wx         : 0.f;
    float w10 = (vy1 && vx0) ? wy * (1.f - wx)         : 0.f;
    float w11 = (vy1 && vx1) ? wy * wx                 : 0.f;
    ulonglong2 v00 = xb[(size_t)((y0c + 1) * PH_ + (x0c + 1)) * 4];
    ulonglong2 v01 = xb[(size_t)((y0c + 1) * PH_ + (x1c + 1)) * 4];
    ulonglong2 v10 = xb[(size_t)((y1c + 1) * PH_ + (x0c + 1)) * 4];
    ulonglong2 v11 = xb[(size_t)((y1c + 1) * PH_ + (x1c + 1)) * 4];
    unsigned long long p00 = pack2(w00, w00), p01 = pack2(w01, w01);
    unsigned long long p10 = pack2(w10, w10), p11 = pack2(w11, w11);
    s0 = 0ULL; s1 = 0ULL;
    fma2(s0, p00, v00.x); fma2(s1, p00, v00.y);
    fma2(s0, p01, v01.x); fma2(s1, p01, v01.y);
    fma2(s0, p10, v10.x); fma2(s1, p10, v10.y);
    fma2(s0, p11, v11.x); fma2(s1, p11, v11.y);
}

// ---------------- K1: FUSED offsets + deformable conv + BN partial stats ----
// grid (H, G, B), 256 threads.
// Phase A (tid<128): 4-pos offset computation -> s_off in shared
// Phase B (all 256): 2-pos deform (R6 packed dataflow), offsets from shared,
//                    per-channel sum/sumsq accumulated on the storing lane.
__global__ void __launch_bounds__(256, 2) k_fused(const float* __restrict__ tm_w,
                                                  const float* __restrict__ tm_b,
                                                  const float* __restrict__ dc_w) {
    __shared__ __align__(16) float wsa[6*9*16];    // offsets weights [(a*9+t)*16 + c]
    __shared__ __align__(16) float ws[9*16*16];    // deform weights [(k*16+o)*16 + c]
    __shared__ __align__(16) float2 s_off[9*128];  // per-row offsets [k][w]
    __shared__ float sSum[16], sSq[16];
    const int g = blockIdx.y, b = blockIdx.z;
    const int h = blockIdx.x;
    const int tid = threadIdx.x;
    const int bg = b*G_ + g;

    for (int i = tid; i < 864; i += 256) {
        int a = i / 144, rem = i - a*144, t = rem >> 4, c = rem & 15;
        int ch = (a >= 3 ? 51 : 0) + (a % 3) * 17 + g;   // i*3G + j*G + g
        wsa[i] = tm_w[((size_t)ch*16 + c)*9 + t];
    }
    for (int i = tid; i < 2304; i += 256) {
        int k = i >> 8, o = (i >> 4) & 15, c = i & 15;
        ws[i] = dc_w[(((size_t)g*16 + o)*16 + c)*9 + k];
    }
    if (tid < 16) { sSum[tid] = 0.f; sSq[tid] = 0.f; }
    __syncthreads();

    // ===== Phase A: offsets (threads 0..127; 32 wslots x 4 q, 4 pos/thread) =====
    if (tid < 128) {
        const int wslot = tid >> 2, q = tid & 3;

        unsigned long long acc[4][6];
        #pragma unroll
        for (int j = 0; j < 4; j++)
            #pragma unroll
            for (int a = 0; a < 6; a++) acc[j][a] = 0ULL;

        int chs[6];
        #pragma unroll
        for (int a = 0; a < 6; a++) {
            const int ch = (a >= 3 ? 51 : 0) + (a % 3) * 17 + g;
            chs[a] = ch;
            const int cg = ch / 6;   // conv group of this output channel (NOT g)
            const ulonglong2* xb = reinterpret_cast<const ulonglong2*>(g_xT)
                                 + (size_t)(b*G_ + cg) * PHW_ * 4 + q;
            #pragma unroll
            for (int t = 0; t < 9; t++) {
                const int lin = (h + t/3) * PH_ + (wslot + t%3);
                ulonglong2 wv = *reinterpret_cast<const ulonglong2*>(&wsa[(a*9 + t)*16 + 4*q]);
                #pragma unroll
                for (int j = 0; j < 4; j++) {
                    ulonglong2 v = xb[(size_t)(lin + 32*j) * 4];
                    fma2(acc[j][a], v.x, wv.x);
                    fma2(acc[j][a], v.y, wv.y);
                }
            }
        }

        float aff[4][6];
        #pragma unroll
        for (int a = 0; a < 6; a++) {
            float bias = tm_b[chs[a]];
            #pragma unroll
            for (int j = 0; j < 4; j++) {
                float2 p = unpack2(acc[j][a]);
                float v = p.x + p.y;
                v += __shfl_xor_sync(0xffffffffu, v, 1);
                v += __shfl_xor_sync(0xffffffffu, v, 2);
                aff[j][a] = v + bias;
            }
        }

        // flat slot j: j<9 -> rowY[j], j>=9 -> rowX[j-9]; tap kk = (flat[2kk],flat[2kk+1])
        #pragma unroll
        for (int kk = 0; kk < 9; kk++) {
            if ((kk & 3) != q) continue;
            const int jy = 2*kk, jx = 2*kk + 1;
            const int ty = (jy < 9) ? jy : jy - 9;
            const int tx = (jx < 9) ? jx : jx - 9;
            const float kyy = (float)(ty/3 - 1), kyx = (float)(ty%3 - 1);
            const float kxy = (float)(tx/3 - 1), kxx = (float)(tx%3 - 1);
            #pragma unroll
            for (int j = 0; j < 4; j++) {
                float fy = (jy < 9)
                    ? fmaf(aff[j][0], kyy, fmaf(aff[j][1], kyx, aff[j][2]))
                    : fmaf(aff[j][3], kyy, fmaf(aff[j][4], kyx, aff[j][5]));
                float fx = (jx < 9)
                    ? fmaf(aff[j][0], kxy, fmaf(aff[j][1], kxx, aff[j][2]))
                    : fmaf(aff[j][3], kxy, fmaf(aff[j][4], kxx, aff[j][5]));
                s_off[kk * 128 + wslot + 32*j] = make_float2(fy, fx);
            }
        }
    }
    __syncthreads();

    // ===== Phase B: deform (all 256 threads; 64 wslots x 4 q, 2 pos/thread) =====
    const int wslot = tid >> 2, q = tid & 3;
    const int w0 = wslot, w1 = wslot + 64;
    const ulonglong2* xb = reinterpret_cast<const ulonglong2*>(g_xT)
                         + (size_t)bg * PHW_ * 4 + q;

    unsigned long long accA[16], accB[16];
    #pragma unroll
    for (int o = 0; o < 16; o++) { accA[o] = 0ULL; accB[o] = 0ULL; }

    #pragma unroll
    for (int k = 0; k < 9; k++) {
        float2 oa  = s_off[k * 128 + w0];
        float2 obx = s_off[k * 128 + w1];
        const int ky = k/3 - 1, kx = k%3 - 1;
        unsigned long long s0a, s1a, s0b, s1b;
        bilin_gather(xb, oa,  h, w0, ky, kx, s0a, s1a);
        bilin_gather(xb, obx, h, w1, ky, kx, s0b, s1b);
        const float* wk = ws + k*256 + 4*q;
        #pragma unroll
        for (int o = 0; o < 16; o++) {
            ulonglong2 wv = *reinterpret_cast<const ulonglong2*>(wk + o*16);
            fma2(accA[o], s0a, wv.x);
            fma2(accA[o], s1a, wv.y);
            fma2(accB[o], s0b, wv.x);
            fma2(accB[o], s1b, wv.y);
        }
    }

    // cross-lane reduce, store, and per-channel stats on the storing lane
    float st_s[4], st_q[4];
    #pragma unroll
    for (int i = 0; i < 4; i++) { st_s[i] = 0.f; st_q[i] = 0.f; }

    float* outp = g_conv + ((size_t)b*C_ + g*16) * HW_ + h * W_;
    #pragma unroll
    for (int o = 0; o < 16; o++) {
        float2 pA = unpack2(accA[o]);
        float2 pB = unpack2(accB[o]);
        float a0 = pA.x + pA.y, a1 = pB.x + pB.y;
        a0 += __shfl_xor_sync(0xffffffffu, a0, 1);
        a0 += __shfl_xor_sync(0xffffffffu, a0, 2);
        a1 += __shfl_xor_sync(0xffffffffu, a1, 1);
        a1 += __shfl_xor_sync(0xffffffffu, a1, 2);
        if ((o >> 2) == q) {
            outp[(size_t)o * HW_ + w0] = a0;
            outp[(size_t)o * HW_ + w1] = a1;
            st_s[o & 3] += a0 + a1;
            st_q[o & 3] = fmaf(a0, a0, st_q[o & 3]);
            st_q[o & 3] = fmaf(a1, a1, st_q[o & 3]);
        }
    }

    // reduce stats over the 8 lanes with the same q (strides 4, 8, 16), packed
    unsigned long long ps0 = pack2(st_s[0], st_s[1]);
    unsigned long long ps1 = pack2(st_s[2], st_s[3]);
    unsigned long long pq0 = pack2(st_q[0], st_q[1]);
    unsigned long long pq1 = pack2(st_q[2], st_q[3]);
    #pragma unroll
    for (int st = 4; st <= 16; st <<= 1) {
        float2 a, bb;
        a = unpack2(ps0); bb = unpack2(__shfl_xor_sync(0xffffffffu, ps0, st));
        ps0 = pack2(a.x + bb.x, a.y + bb.y);
        a = unpack2(ps1); bb = unpack2(__shfl_xor_sync(0xffffffffu, ps1, st));
        ps1 = pack2(a.x + bb.x, a.y + bb.y);
        a = unpack2(pq0); bb = unpack2(__shfl_xor_sync(0xffffffffu, pq0, st));
        pq0 = pack2(a.x + bb.x, a.y + bb.y);
        a = unpack2(pq1); bb = unpack2(__shfl_xor_sync(0xffffffffu, pq1, st));
        pq1 = pack2(a.x + bb.x, a.y + bb.y);
    }
    if ((tid & 31) < 4) {   // lanes 0..3 hold q=0..3 reduced values
        float2 s01 = unpack2(ps0), s23 = unpack2(ps1);
        float2 q01 = unpack2(pq0), q23 = unpack2(pq1);
        atomicAdd(&sSum[4*q + 0], s01.x);
        atomicAdd(&sSum[4*q + 1], s01.y);
        atomicAdd(&sSum[4*q + 2], s23.x);
        atomicAdd(&sSum[4*q + 3], s23.y);
        atomicAdd(&sSq[4*q + 0], q01.x);
        atomicAdd(&sSq[4*q + 1], q01.y);
        atomicAdd(&sSq[4*q + 2], q23.x);
        atomicAdd(&sSq[4*q + 3], q23.y);
    }
    __syncthreads();
    if (tid < 16) {
        atomicAdd(&g_sum[g*16 + tid],   sSum[tid]);
        atomicAdd(&g_sumsq[g*16 + tid], sSq[tid]);
    }
}

// ---------------- K2: finalize BN scale/shift ----------------
__global__ void k_scale() {
    int c = threadIdx.x;
    if (c >= C_) return;
    const float invN = 1.f / (float)(B_*HW_);
    float mean = g_sum[c] * invN;
    float var  = g_sumsq[c] * invN - mean * mean;
    g_mean[c] = mean;
    g_istd[c] = rsqrtf(var + 1e-5f);
}

// ---------------- K3: BN apply + residual + ReLU ----------------
__global__ void k_final(const float* __restrict__ x, const float* __restrict__ gamma,
                        const float* __restrict__ beta, float* __restrict__ out) {
    int i = blockIdx.x * blockDim.x + threadIdx.x;
    const int total4 = B_*C_*HW_/4;
    if (i >= total4) return;
    int c = (i >> 12) % C_;
    float sc = g_istd[c] * gamma[c];
    float sh = beta[c] - g_mean[c] * sc;
    float4 v  = reinterpret_cast<const float4*>(g_conv)[i];
    float4 xv = reinterpret_cast<const float4*>(x)[i];
    float4 r;
    r.x = fmaxf(fmaf(v.x, sc, sh) + xv.x, 0.f);
    r.y = fmaxf(fmaf(v.y, sc, sh) + xv.y, 0.f);
    r.z = fmaxf(fmaf(v.z, sc, sh) + xv.z, 0.f);
    r.w = fmaxf(fmaf(v.w, sc, sh) + xv.w, 0.f);
    reinterpret_cast<float4*>(out)[i] = r;
}

// ---------------- launch ----------------
extern "C" void kernel_launch(void* const* d_in, const int* in_sizes, int n_in,
                              void* d_out, int out_size) {
    const float* x     = (const float*)d_in[0];
    const float* tm_w  = (const float*)d_in[1];
    const float* tm_b  = (const float*)d_in[2];
    const float* dc_w  = (const float*)d_in[3];
    const float* gamma = (const float*)d_in[4];
    const float* beta  = (const float*)d_in[5];
    float* out = (float*)d_out;

    k_zero<<<(B_*G_*516*4 + 255)/256, 256>>>();
    k_transpose<<<dim3(HW_/256, B_*G_), 256>>>(x);
    k_fused<<<dim3(H_, G_, B_), 256>>>(tm_w, tm_b, dc_w);
    k_scale<<<1, 512>>>();
    k_final<<<(B_*C_*HW_/4 + 255)/256, 256>>>(x, gamma, beta, out);
}

// round 12
// speedup vs baseline: 1.0200x; 1.0200x over previous
#include <cuda_runtime.h>

#define B_  2
#define C_  272
#define H_  128
#define W_  128
#define G_  17
#define CG_ 16
#define HW_ (H_*W_)
#define PH_ 130
#define PHW_ (PH_*PH_)   // padded plane 130x130

// ---------------- scratch (device globals; no allocation) ----------------
__device__ __align__(16) float g_xT[B_*G_*PHW_*CG_];    // (b,g, padpos, c16), zero halo
__device__ __align__(16) float g_conv[B_*C_*HW_];       // (B,C,H,W)
__device__ float g_mean[C_];
__device__ float g_istd[C_];

// ---------------- packed f32x2 helpers ----------------
__device__ __forceinline__ unsigned long long pack2(float lo, float hi) {
    unsigned long long r;
    asm("mov.b64 %0, {%1,%2};" : "=l"(r) : "f"(lo), "f"(hi));
    return r;
}
__device__ __forceinline__ float2 unpack2(unsigned long long v) {
    float2 r;
    asm("mov.b64 {%0,%1}, %2;" : "=f"(r.x), "=f"(r.y) : "l"(v));
    return r;
}
__device__ __forceinline__ void fma2(unsigned long long& d,
                                     unsigned long long a, unsigned long long b) {
    asm("fma.rn.f32x2 %0, %1, %2, %0;" : "+l"(d) : "l"(a), "l"(b));
}

// ---------------- K-1: zero the halo of g_xT ----------
__global__ void k_zero() {
    int t = blockIdx.x * blockDim.x + threadIdx.x;
    const int total = B_*G_ * 516 * 4;   // 516 halo cells per plane, 4 quads
    if (t >= total) return;
    int c4 = t & 3, cell = t >> 2;
    int bg = cell / 516, p = cell - bg * 516;
    int y, x;
    if (p < 130)      { y = 0;   x = p; }
    else if (p < 260) { y = 129; x = p - 130; }
    else { int r = p - 260; y = 1 + (r >> 1); x = (r & 1) * 129; }
    float4* dst = reinterpret_cast<float4*>(g_xT)
                + ((size_t)bg * PHW_ + y * PH_ + x) * 4 + c4;
    *dst = make_float4(0.f, 0.f, 0.f, 0.f);
}

// ---------------- K0: transpose x (B,C,H,W) -> padded (b,g,pady,padx,c16) ----
__global__ void __launch_bounds__(256) k_transpose(const float* __restrict__ x) {
    __shared__ float sh[16 * 257];
    const int bg   = blockIdx.y;
    const int base = blockIdx.x * 256;       // 256 positions = 2 rows
    const float* src = x + (size_t)bg * 16 * HW_ + base;
    #pragma unroll
    for (int c = 0; c < 16; c++)
        sh[c * 257 + threadIdx.x] = src[(size_t)c * HW_ + threadIdx.x];
    __syncthreads();
    float4* dst = reinterpret_cast<float4*>(g_xT);
    #pragma unroll
    for (int it = 0; it < 4; it++) {
        int idx = it * 256 + threadIdx.x;
        int p = idx >> 2, q = idx & 3;
        int pos = base + p;
        int h = pos >> 7, w = pos & (W_ - 1);
        float4 v;
        v.x = sh[(4*q + 0) * 257 + p];
        v.y = sh[(4*q + 1) * 257 + p];
        v.z = sh[(4*q + 2) * 257 + p];
        v.w = sh[(4*q + 3) * 257 + p];
        dst[((size_t)bg * PHW_ + (h + 1) * PH_ + (w + 1)) * 4 + q] = v;
    }
}

// ---------------- bilinear gather (R6 exact, packed dataflow) ----------------
__device__ __forceinline__ void bilin_gather(const ulonglong2* __restrict__ xb,
                                             float2 off, int h, int w,
                                             int ky, int kx,
                                             unsigned long long& s0,
                                             unsigned long long& s1) {
    float py = (float)(h + ky) + off.x;
    float px = (float)(w + kx) + off.y;
    float y0f = floorf(py), x0f = floorf(px);
    float wy = py - y0f, wx = px - x0f;
    int y0 = (int)y0f, x0 = (int)x0f;
    int y1 = y0 + 1, x1 = x0 + 1;
    bool vy0 = (unsigned)y0 < H_, vy1 = (unsigned)y1 < H_;
    bool vx0 = (unsigned)x0 < W_, vx1 = (unsigned)x1 < W_;
    int y0c = min(max(y0, 0), H_-1), y1c = min(max(y1, 0), H_-1);
    int x0c = min(max(x0, 0), W_-1), x1c = min(max(x1, 0), W_-1);
    float w00 = (vy0 && vx0) ? (1.f - wy) * (1.f - wx) : 0.f;
    float w01 = (vy0 && vx1) ? (1.f - wy) * wx         : 0.f;
    float w10 = (vy1 && vx0) ? wy * (1.f - wx)         : 0.f;
    float w11 = (vy1 && vx1) ? wy * wx                 : 0.f;
    ulonglong2 v00 = xb[(size_t)((y0c + 1) * PH_ + (x0c + 1)) * 4];
    ulonglong2 v01 = xb[(size_t)((y0c + 1) * PH_ + (x1c + 1)) * 4];
    ulonglong2 v10 = xb[(size_t)((y1c + 1) * PH_ + (x0c + 1)) * 4];
    ulonglong2 v11 = xb[(size_t)((y1c + 1) * PH_ + (x1c + 1)) * 4];
    unsigned long long p00 = pack2(w00, w00), p01 = pack2(w01, w01);
    unsigned long long p10 = pack2(w10, w10), p11 = pack2(w11, w11);
    s0 = 0ULL; s1 = 0ULL;
    fma2(s0, p00, v00.x); fma2(s1, p00, v00.y);
    fma2(s0, p01, v01.x); fma2(s1, p01, v01.y);
    fma2(s0, p10, v10.x); fma2(s1, p10, v10.y);
    fma2(s0, p11, v11.x); fma2(s1, p11, v11.y);
}

// ---------------- K1: FUSED offsets + deformable conv ----------------
// grid (H, G, B), 256 threads.
// Phase A (ALL 256 threads; 64 wslots x 4 q, 2 pos/thread): offsets -> s_off
// Phase B (all 256): R6 2-pos deform, offsets read from shared
__global__ void __launch_bounds__(256, 2) k_fused(const float* __restrict__ tm_w,
                                                  const float* __restrict__ tm_b,
                                                  const float* __restrict__ dc_w) {
    __shared__ __align__(16) float wsa[6*9*16];    // offsets weights [(a*9+t)*16 + c]
    __shared__ __align__(16) float ws[9*16*16];    // deform weights [(k*16+o)*16 + c]
    __shared__ __align__(16) float2 s_off[9*128];  // per-row offsets [k][w]
    const int g = blockIdx.y, b = blockIdx.z;
    const int h = blockIdx.x;
    const int tid = threadIdx.x;
    const int bg = b*G_ + g;
    const int wslot = tid >> 2, q = tid & 3;
    const int w0 = wslot, w1 = wslot + 64;

    for (int i = tid; i < 864; i += 256) {
        int a = i / 144, rem = i - a*144, t = rem >> 4, c = rem & 15;
        int ch = (a >= 3 ? 51 : 0) + (a % 3) * 17 + g;   // i*3G + j*G + g
        wsa[i] = tm_w[((size_t)ch*16 + c)*9 + t];
    }
    for (int i = tid; i < 2304; i += 256) {
        int k = i >> 8, o = (i >> 4) & 15, c = i & 15;
        ws[i] = dc_w[(((size_t)g*16 + o)*16 + c)*9 + k];
    }
    __syncthreads();

    // ===== Phase A: offsets (all 256 threads; 2 pos/thread, R4 math) =====
    {
        unsigned long long acc0[6], acc1[6];
        #pragma unroll
        for (int a = 0; a < 6; a++) { acc0[a] = 0ULL; acc1[a] = 0ULL; }

        int chs[6];
        #pragma unroll
        for (int a = 0; a < 6; a++) {
            const int ch = (a >= 3 ? 51 : 0) + (a % 3) * 17 + g;
            chs[a] = ch;
            const int cg = ch / 6;   // conv group of this output channel (NOT g)
            const ulonglong2* xo = reinterpret_cast<const ulonglong2*>(g_xT)
                                 + (size_t)(b*G_ + cg) * PHW_ * 4 + q;
            #pragma unroll
            for (int t = 0; t < 9; t++) {
                const int lin = (h + t/3) * PH_ + (w0 + t%3);
                ulonglong2 v0 = xo[(size_t)lin * 4];
                ulonglong2 v1 = xo[(size_t)(lin + 64) * 4];
                ulonglong2 wv = *reinterpret_cast<const ulonglong2*>(&wsa[(a*9 + t)*16 + 4*q]);
                fma2(acc0[a], v0.x, wv.x);
                fma2(acc0[a], v0.y, wv.y);
                fma2(acc1[a], v1.x, wv.x);
                fma2(acc1[a], v1.y, wv.y);
            }
        }

        float aff0[6], aff1[6];
        #pragma unroll
        for (int a = 0; a < 6; a++) {
            float2 p0 = unpack2(acc0[a]);
            float2 p1 = unpack2(acc1[a]);
            float v0 = p0.x + p0.y, v1 = p1.x + p1.y;
            v0 += __shfl_xor_sync(0xffffffffu, v0, 1);
            v0 += __shfl_xor_sync(0xffffffffu, v0, 2);
            v1 += __shfl_xor_sync(0xffffffffu, v1, 1);
            v1 += __shfl_xor_sync(0xffffffffu, v1, 2);
            float bias = tm_b[chs[a]];
            aff0[a] = v0 + bias;
            aff1[a] = v1 + bias;
        }

        // flat slot j: j<9 -> rowY[j], j>=9 -> rowX[j-9]; tap kk = (flat[2kk],flat[2kk+1])
        #pragma unroll
        for (int kk = 0; kk < 9; kk++) {
            if ((kk & 3) != q) continue;
            const int jy = 2*kk, jx = 2*kk + 1;
            const int ty = (jy < 9) ? jy : jy - 9;
            const int tx = (jx < 9) ? jx : jx - 9;
            const float kyy = (float)(ty/3 - 1), kyx = (float)(ty%3 - 1);
            const float kxy = (float)(tx/3 - 1), kxx = (float)(tx%3 - 1);
            float fy0 = (jy < 9)
                ? fmaf(aff0[0], kyy, fmaf(aff0[1], kyx, aff0[2]))
                : fmaf(aff0[3], kyy, fmaf(aff0[4], kyx, aff0[5]));
            float fx0 = (jx < 9)
                ? fmaf(aff0[0], kxy, fmaf(aff0[1], kxx, aff0[2]))
                : fmaf(aff0[3], kxy, fmaf(aff0[4], kxx, aff0[5]));
            float fy1 = (jy < 9)
                ? fmaf(aff1[0], kyy, fmaf(aff1[1], kyx, aff1[2]))
                : fmaf(aff1[3], kyy, fmaf(aff1[4], kyx, aff1[5]));
            float fx1 = (jx < 9)
                ? fmaf(aff1[0], kxy, fmaf(aff1[1], kxx, aff1[2]))
                : fmaf(aff1[3], kxy, fmaf(aff1[4], kxx, aff1[5]));
            s_off[kk * 128 + w0] = make_float2(fy0, fx0);
            s_off[kk * 128 + w1] = make_float2(fy1, fx1);
        }
    }
    __syncthreads();

    // ===== Phase B: deform (all 256 threads; 64 wslots x 4 q, 2 pos/thread) =====
    const ulonglong2* xb = reinterpret_cast<const ulonglong2*>(g_xT)
                         + (size_t)bg * PHW_ * 4 + q;

    unsigned long long accA[16], accB[16];
    #pragma unroll
    for (int o = 0; o < 16; o++) { accA[o] = 0ULL; accB[o] = 0ULL; }

    #pragma unroll
    for (int k = 0; k < 9; k++) {
        float2 oa  = s_off[k * 128 + w0];
        float2 obx = s_off[k * 128 + w1];
        const int ky = k/3 - 1, kx = k%3 - 1;
        unsigned long long s0a, s1a, s0b, s1b;
        bilin_gather(xb, oa,  h, w0, ky, kx, s0a, s1a);
        bilin_gather(xb, obx, h, w1, ky, kx, s0b, s1b);
        const float* wk = ws + k*256 + 4*q;
        #pragma unroll
        for (int o = 0; o < 16; o++) {
            ulonglong2 wv = *reinterpret_cast<const ulonglong2*>(wk + o*16);
            fma2(accA[o], s0a, wv.x);
            fma2(accA[o], s1a, wv.y);
            fma2(accB[o], s0b, wv.x);
            fma2(accB[o], s1b, wv.y);
        }
    }

    float* outp = g_conv + ((size_t)b*C_ + g*16) * HW_ + h * W_;
    #pragma unroll
    for (int o = 0; o < 16; o++) {
        float2 pA = unpack2(accA[o]);
        float2 pB = unpack2(accB[o]);
        float a0 = pA.x + pA.y, a1 = pB.x + pB.y;
        a0 += __shfl_xor_sync(0xffffffffu, a0, 1);
        a0 += __shfl_xor_sync(0xffffffffu, a0, 2);
        a1 += __shfl_xor_sync(0xffffffffu, a1, 1);
        a1 += __shfl_xor_sync(0xffffffffu, a1, 2);
        if ((o >> 2) == q) {
            outp[(size_t)o * HW_ + w0] = a0;
            outp[(size_t)o * HW_ + w1] = a1;
        }
    }
}

// ---------------- K3: per-channel BN statistics (1024 threads, float4) -----
__global__ void __launch_bounds__(1024) k_stats() {
    const int c = blockIdx.x;
    const float4* p0 = reinterpret_cast<const float4*>(g_conv + (size_t)c * HW_);
    const float4* p1 = reinterpret_cast<const float4*>(g_conv + (size_t)(C_ + c) * HW_);
    float s = 0.f, s2 = 0.f;
    #pragma unroll
    for (int it = 0; it < 4; it++) {
        int i = it * 1024 + threadIdx.x;
        float4 v0 = p0[i], v1 = p1[i];
        s  += v0.x + v0.y + v0.z + v0.w + v1.x + v1.y + v1.z + v1.w;
        s2 = fmaf(v0.x, v0.x, s2); s2 = fmaf(v0.y, v0.y, s2);
        s2 = fmaf(v0.z, v0.z, s2); s2 = fmaf(v0.w, v0.w, s2);
        s2 = fmaf(v1.x, v1.x, s2); s2 = fmaf(v1.y, v1.y, s2);
        s2 = fmaf(v1.z, v1.z, s2); s2 = fmaf(v1.w, v1.w, s2);
    }
    __shared__ float sh[2048];
    sh[threadIdx.x] = s;
    sh[1024 + threadIdx.x] = s2;
    __syncthreads();
    for (int st = 512; st > 0; st >>= 1) {
        if (threadIdx.x < st) {
            sh[threadIdx.x]        += sh[threadIdx.x + st];
            sh[1024 + threadIdx.x] += sh[1024 + threadIdx.x + st];
        }
        __syncthreads();
    }
    if (threadIdx.x == 0) {
        const float invN = 1.f / (float)(B_*HW_);
        float mean = sh[0] * invN;
        float var  = sh[1024] * invN - mean * mean;
        g_mean[c] = mean;
        g_istd[c] = rsqrtf(var + 1e-5f);
    }
}

// ---------------- K4: BN apply + residual + ReLU ----------------
__global__ void k_final(const float* __restrict__ x, const float* __restrict__ gamma,
                        const float* __restrict__ beta, float* __restrict__ out) {
    int i = blockIdx.x * blockDim.x + threadIdx.x;
    const int total4 = B_*C_*HW_/4;
    if (i >= total4) return;
    int c = (i >> 12) % C_;
    float sc = g_istd[c] * gamma[c];
    float sh = beta[c] - g_mean[c] * sc;
    float4 v  = reinterpret_cast<const float4*>(g_conv)[i];
    float4 xv = reinterpret_cast<const float4*>(x)[i];
    float4 r;
    r.x = fmaxf(fmaf(v.x, sc, sh) + xv.x, 0.f);
    r.y = fmaxf(fmaf(v.y, sc, sh) + xv.y, 0.f);
    r.z = fmaxf(fmaf(v.z, sc, sh) + xv.z, 0.f);
    r.w = fmaxf(fmaf(v.w, sc, sh) + xv.w, 0.f);
    reinterpret_cast<float4*>(out)[i] = r;
}

// ---------------- launch ----------------
extern "C" void kernel_launch(void* const* d_in, const int* in_sizes, int n_in,
                              void* d_out, int out_size) {
    const float* x     = (const float*)d_in[0];
    const float* tm_w  = (const float*)d_in[1];
    const float* tm_b  = (const float*)d_in[2];
    const float* dc_w  = (const float*)d_in[3];
    const float* gamma = (const float*)d_in[4];
    const float* beta  = (const float*)d_in[5];
    float* out = (float*)d_out;

    k_zero<<<(B_*G_*516*4 + 255)/256, 256>>>();
    k_transpose<<<dim3(HW_/256, B_*G_), 256>>>(x);
    k_fused<<<dim3(H_, G_, B_), 256>>>(tm_w, tm_b, dc_w);
    k_stats<<<C_, 1024>>>();
    k_final<<<(B_*C_*HW_/4 + 255)/256, 256>>>(x, gamma, beta, out);
}

// round 13
// speedup vs baseline: 1.0338x; 1.0135x over previous
#include <cuda_runtime.h>

#define B_  2
#define C_  272
#define H_  128
#define W_  128
#define G_  17
#define CG_ 16
#define HW_ (H_*W_)
#define PH_ 130
#define PHW_ (PH_*PH_)   // padded plane 130x130

// ---------------- scratch (device globals; no allocation) ----------------
__device__ __align__(16) float g_xT[B_*G_*PHW_*CG_];    // (b,g, padpos, c16), zero halo
__device__ __align__(16) float g_conv[B_*C_*HW_];       // (B,C,H,W)
__device__ float g_mean[C_];
__device__ float g_istd[C_];

// ---------------- packed f32x2 helpers ----------------
__device__ __forceinline__ unsigned long long pack2(float lo, float hi) {
    unsigned long long r;
    asm("mov.b64 %0, {%1,%2};" : "=l"(r) : "f"(lo), "f"(hi));
    return r;
}
__device__ __forceinline__ float2 unpack2(unsigned long long v) {
    float2 r;
    asm("mov.b64 {%0,%1}, %2;" : "=f"(r.x), "=f"(r.y) : "l"(v));
    return r;
}
__device__ __forceinline__ void fma2(unsigned long long& d,
                                     unsigned long long a, unsigned long long b) {
    asm("fma.rn.f32x2 %0, %1, %2, %0;" : "+l"(d) : "l"(a), "l"(b));
}

// ---------------- K0: transpose x -> padded (b,g,pady,padx,c16) + halo zero -
__global__ void __launch_bounds__(256) k_transpose(const float* __restrict__ x) {
    __shared__ float sh[16 * 257];
    const int bg   = blockIdx.y;
    const int base = blockIdx.x * 256;       // 256 positions = 2 rows

    // block x==0 also zeroes this plane's halo (516 border cells x 4 quads)
    if (blockIdx.x == 0) {
        float4* hz = reinterpret_cast<float4*>(g_xT) + (size_t)bg * PHW_ * 4;
        for (int i = threadIdx.x; i < 516 * 4; i += 256) {
            int c4 = i & 3, p = i >> 2;
            int y, xx;
            if (p < 130)      { y = 0;   xx = p; }
            else if (p < 260) { y = 129; xx = p - 130; }
            else { int r = p - 260; y = 1 + (r >> 1); xx = (r & 1) * 129; }
            hz[(size_t)(y * PH_ + xx) * 4 + c4] = make_float4(0.f, 0.f, 0.f, 0.f);
        }
    }

    const float* src = x + (size_t)bg * 16 * HW_ + base;
    #pragma unroll
    for (int c = 0; c < 16; c++)
        sh[c * 257 + threadIdx.x] = src[(size_t)c * HW_ + threadIdx.x];
    __syncthreads();
    float4* dst = reinterpret_cast<float4*>(g_xT);
    #pragma unroll
    for (int it = 0; it < 4; it++) {
        int idx = it * 256 + threadIdx.x;
        int p = idx >> 2, q = idx & 3;
        int pos = base + p;
        int h = pos >> 7, w = pos & (W_ - 1);
        float4 v;
        v.x = sh[(4*q + 0) * 257 + p];
        v.y = sh[(4*q + 1) * 257 + p];
        v.z = sh[(4*q + 2) * 257 + p];
        v.w = sh[(4*q + 3) * 257 + p];
        dst[((size_t)bg * PHW_ + (h + 1) * PH_ + (w + 1)) * 4 + q] = v;
    }
}

// ---------------- bilinear gather (R6 exact, packed dataflow) ----------------
__device__ __forceinline__ void bilin_gather(const ulonglong2* __restrict__ xb,
                                             float2 off, int h, int w,
                                             int ky, int kx,
                                             unsigned long long& s0,
                                             unsigned long long& s1) {
    float py = (float)(h + ky) + off.x;
    float px = (float)(w + kx) + off.y;
    float y0f = floorf(py), x0f = floorf(px);
    float wy = py - y0f, wx = px - x0f;
    int y0 = (int)y0f, x0 = (int)x0f;
    int y1 = y0 + 1, x1 = x0 + 1;
    bool vy0 = (unsigned)y0 < H_, vy1 = (unsigned)y1 < H_;
    bool vx0 = (unsigned)x0 < W_, vx1 = (unsigned)x1 < W_;
    int y0c = min(max(y0, 0), H_-1), y1c = min(max(y1, 0), H_-1);
    int x0c = min(max(x0, 0), W_-1), x1c = min(max(x1, 0), W_-1);
    float w00 = (vy0 && vx0) ? (1.f - wy) * (1.f - wx) : 0.f;
    float w01 = (vy0 && vx1) ? (1.f - wy) * wx         : 0.f;
    float w10 = (vy1 && vx0) ? wy * (1.f - wx)         : 0.f;
    float w11 = (vy1 && vx1) ? wy * wx                 : 0.f;
    ulonglong2 v00 = xb[(size_t)((y0c + 1) * PH_ + (x0c + 1)) * 4];
    ulonglong2 v01 = xb[(size_t)((y0c + 1) * PH_ + (x1c + 1)) * 4];
    ulonglong2 v10 = xb[(size_t)((y1c + 1) * PH_ + (x0c + 1)) * 4];
    ulonglong2 v11 = xb[(size_t)((y1c + 1) * PH_ + (x1c + 1)) * 4];
    unsigned long long p00 = pack2(w00, w00), p01 = pack2(w01, w01);
    unsigned long long p10 = pack2(w10, w10), p11 = pack2(w11, w11);
    s0 = 0ULL; s1 = 0ULL;
    fma2(s0, p00, v00.x); fma2(s1, p00, v00.y);
    fma2(s0, p01, v01.x); fma2(s1, p01, v01.y);
    fma2(s0, p10, v10.x); fma2(s1, p10, v10.y);
    fma2(s0, p11, v11.x); fma2(s1, p11, v11.y);
}

// ---------------- K1: FUSED offsets + deformable conv (R12 exact) ----------
__global__ void __launch_bounds__(256, 2) k_fused(const float* __restrict__ tm_w,
                                                  const float* __restrict__ tm_b,
                                                  const float* __restrict__ dc_w) {
    __shared__ __align__(16) float wsa[6*9*16];    // offsets weights [(a*9+t)*16 + c]
    __shared__ __align__(16) float ws[9*16*16];    // deform weights [(k*16+o)*16 + c]
    __shared__ __align__(16) float2 s_off[9*128];  // per-row offsets [k][w]
    const int g = blockIdx.y, b = blockIdx.z;
    const int h = blockIdx.x;
    const int tid = threadIdx.x;
    const int bg = b*G_ + g;
    const int wslot = tid >> 2, q = tid & 3;
    const int w0 = wslot, w1 = wslot + 64;

    for (int i = tid; i < 864; i += 256) {
        int a = i / 144, rem = i - a*144, t = rem >> 4, c = rem & 15;
        int ch = (a >= 3 ? 51 : 0) + (a % 3) * 17 + g;   // i*3G + j*G + g
        wsa[i] = tm_w[((size_t)ch*16 + c)*9 + t];
    }
    for (int i = tid; i < 2304; i += 256) {
        int k = i >> 8, o = (i >> 4) & 15, c = i & 15;
        ws[i] = dc_w[(((size_t)g*16 + o)*16 + c)*9 + k];
    }
    __syncthreads();

    // ===== Phase A: offsets (all 256 threads; 2 pos/thread) =====
    {
        unsigned long long acc0[6], acc1[6];
        #pragma unroll
        for (int a = 0; a < 6; a++) { acc0[a] = 0ULL; acc1[a] = 0ULL; }

        int chs[6];
        #pragma unroll
        for (int a = 0; a < 6; a++) {
            const int ch = (a >= 3 ? 51 : 0) + (a % 3) * 17 + g;
            chs[a] = ch;
            const int cg = ch / 6;   // conv group of this output channel (NOT g)
            const ulonglong2* xo = reinterpret_cast<const ulonglong2*>(g_xT)
                                 + (size_t)(b*G_ + cg) * PHW_ * 4 + q;
            #pragma unroll
            for (int t = 0; t < 9; t++) {
                const int lin = (h + t/3) * PH_ + (w0 + t%3);
                ulonglong2 v0 = xo[(size_t)lin * 4];
                ulonglong2 v1 = xo[(size_t)(lin + 64) * 4];
                ulonglong2 wv = *reinterpret_cast<const ulonglong2*>(&wsa[(a*9 + t)*16 + 4*q]);
                fma2(acc0[a], v0.x, wv.x);
                fma2(acc0[a], v0.y, wv.y);
                fma2(acc1[a], v1.x, wv.x);
                fma2(acc1[a], v1.y, wv.y);
            }
        }

        float aff0[6], aff1[6];
        #pragma unroll
        for (int a = 0; a < 6; a++) {
            float2 p0 = unpack2(acc0[a]);
            float2 p1 = unpack2(acc1[a]);
            float v0 = p0.x + p0.y, v1 = p1.x + p1.y;
            v0 += __shfl_xor_sync(0xffffffffu, v0, 1);
            v0 += __shfl_xor_sync(0xffffffffu, v0, 2);
            v1 += __shfl_xor_sync(0xffffffffu, v1, 1);
            v1 += __shfl_xor_sync(0xffffffffu, v1, 2);
            float bias = tm_b[chs[a]];
            aff0[a] = v0 + bias;
            aff1[a] = v1 + bias;
        }

        #pragma unroll
        for (int kk = 0; kk < 9; kk++) {
            if ((kk & 3) != q) continue;
            const int jy = 2*kk, jx = 2*kk + 1;
            const int ty = (jy < 9) ? jy : jy - 9;
            const int tx = (jx < 9) ? jx : jx - 9;
            const float kyy = (float)(ty/3 - 1), kyx = (float)(ty%3 - 1);
            const float kxy = (float)(tx/3 - 1), kxx = (float)(tx%3 - 1);
            float fy0 = (jy < 9)
                ? fmaf(aff0[0], kyy, fmaf(aff0[1], kyx, aff0[2]))
                : fmaf(aff0[3], kyy, fmaf(aff0[4], kyx, aff0[5]));
            float fx0 = (jx < 9)
                ? fmaf(aff0[0], kxy, fmaf(aff0[1], kxx, aff0[2]))
                : fmaf(aff0[3], kxy, fmaf(aff0[4], kxx, aff0[5]));
            float fy1 = (jy < 9)
                ? fmaf(aff1[0], kyy, fmaf(aff1[1], kyx, aff1[2]))
                : fmaf(aff1[3], kyy, fmaf(aff1[4], kyx, aff1[5]));
            float fx1 = (jx < 9)
                ? fmaf(aff1[0], kxy, fmaf(aff1[1], kxx, aff1[2]))
                : fmaf(aff1[3], kxy, fmaf(aff1[4], kxx, aff1[5]));
            s_off[kk * 128 + w0] = make_float2(fy0, fx0);
            s_off[kk * 128 + w1] = make_float2(fy1, fx1);
        }
    }
    __syncthreads();

    // ===== Phase B: deform (all 256 threads; 2 pos/thread) =====
    const ulonglong2* xb = reinterpret_cast<const ulonglong2*>(g_xT)
                         + (size_t)bg * PHW_ * 4 + q;

    unsigned long long accA[16], accB[16];
    #pragma unroll
    for (int o = 0; o < 16; o++) { accA[o] = 0ULL; accB[o] = 0ULL; }

    #pragma unroll
    for (int k = 0; k < 9; k++) {
        float2 oa  = s_off[k * 128 + w0];
        float2 obx = s_off[k * 128 + w1];
        const int ky = k/3 - 1, kx = k%3 - 1;
        unsigned long long s0a, s1a, s0b, s1b;
        bilin_gather(xb, oa,  h, w0, ky, kx, s0a, s1a);
        bilin_gather(xb, obx, h, w1, ky, kx, s0b, s1b);
        const float* wk = ws + k*256 + 4*q;
        #pragma unroll
        for (int o = 0; o < 16; o++) {
            ulonglong2 wv = *reinterpret_cast<const ulonglong2*>(wk + o*16);
            fma2(accA[o], s0a, wv.x);
            fma2(accA[o], s1a, wv.y);
            fma2(accB[o], s0b, wv.x);
            fma2(accB[o], s1b, wv.y);
        }
    }

    float* outp = g_conv + ((size_t)b*C_ + g*16) * HW_ + h * W_;
    #pragma unroll
    for (int o = 0; o < 16; o++) {
        float2 pA = unpack2(accA[o]);
        float2 pB = unpack2(accB[o]);
        float a0 = pA.x + pA.y, a1 = pB.x + pB.y;
        a0 += __shfl_xor_sync(0xffffffffu, a0, 1);
        a0 += __shfl_xor_sync(0xffffffffu, a0, 2);
        a1 += __shfl_xor_sync(0xffffffffu, a1, 1);
        a1 += __shfl_xor_sync(0xffffffffu, a1, 2);
        if ((o >> 2) == q) {
            outp[(size_t)o * HW_ + w0] = a0;
            outp[(size_t)o * HW_ + w1] = a1;
        }
    }
}

// ---------------- K3: per-channel BN statistics (1024 threads, float4) -----
__global__ void __launch_bounds__(1024) k_stats() {
    const int c = blockIdx.x;
    const float4* p0 = reinterpret_cast<const float4*>(g_conv + (size_t)c * HW_);
    const float4* p1 = reinterpret_cast<const float4*>(g_conv + (size_t)(C_ + c) * HW_);
    float s = 0.f, s2 = 0.f;
    #pragma unroll
    for (int it = 0; it < 2; it++) {
        int i = it * 2048 + threadIdx.x;
        float4 v0 = p0[i],        v1 = p1[i];
        float4 v2 = p0[i + 1024], v3 = p1[i + 1024];
        s  += v0.x + v0.y + v0.z + v0.w + v1.x + v1.y + v1.z + v1.w;
        s  += v2.x + v2.y + v2.z + v2.w + v3.x + v3.y + v3.z + v3.w;
        s2 = fmaf(v0.x, v0.x, s2); s2 = fmaf(v0.y, v0.y, s2);
        s2 = fmaf(v0.z, v0.z, s2); s2 = fmaf(v0.w, v0.w, s2);
        s2 = fmaf(v1.x, v1.x, s2); s2 = fmaf(v1.y, v1.y, s2);
        s2 = fmaf(v1.z, v1.z, s2); s2 = fmaf(v1.w, v1.w, s2);
        s2 = fmaf(v2.x, v2.x, s2); s2 = fmaf(v2.y, v2.y, s2);
        s2 = fmaf(v2.z, v2.z, s2); s2 = fmaf(v2.w, v2.w, s2);
        s2 = fmaf(v3.x, v3.x, s2); s2 = fmaf(v3.y, v3.y, s2);
        s2 = fmaf(v3.z, v3.z, s2); s2 = fmaf(v3.w, v3.w, s2);
    }
    __shared__ float sh[2048];
    sh[threadIdx.x] = s;
    sh[1024 + threadIdx.x] = s2;
    __syncthreads();
    for (int st = 512; st > 0; st >>= 1) {
        if (threadIdx.x < st) {
            sh[threadIdx.x]        += sh[threadIdx.x + st];
            sh[1024 + threadIdx.x] += sh[1024 + threadIdx.x + st];
        }
        __syncthreads();
    }
    if (threadIdx.x == 0) {
        const float invN = 1.f / (float)(B_*HW_);
        float mean = sh[0] * invN;
        float var  = sh[1024] * invN - mean * mean;
        g_mean[c] = mean;
        g_istd[c] = rsqrtf(var + 1e-5f);
    }
}

// ---------------- K4: BN apply + residual + ReLU (2 float4/thread) ---------
__global__ void __launch_bounds__(512) k_final(const float* __restrict__ x,
                                               const float* __restrict__ gamma,
                                               const float* __restrict__ beta,
                                               float* __restrict__ out) {
    const int base = blockIdx.x * 1024 + threadIdx.x;
    #pragma unroll
    for (int it = 0; it < 2; it++) {
        int i = base + it * 512;
        int c = (i >> 12) % C_;
        float sc = g_istd[c] * gamma[c];
        float sh = beta[c] - g_mean[c] * sc;
        float4 v  = reinterpret_cast<const float4*>(g_conv)[i];
        float4 xv = reinterpret_cast<const float4*>(x)[i];
        float4 r;
        r.x = fmaxf(fmaf(v.x, sc, sh) + xv.x, 0.f);
        r.y = fmaxf(fmaf(v.y, sc, sh) + xv.y, 0.f);
        r.z = fmaxf(fmaf(v.z, sc, sh) + xv.z, 0.f);
        r.w = fmaxf(fmaf(v.w, sc, sh) + xv.w, 0.f);
        reinterpret_cast<float4*>(out)[i] = r;
    }
}

// ---------------- launch ----------------
extern "C" void kernel_launch(void* const* d_in, const int* in_sizes, int n_in,
                              void* d_out, int out_size) {
    const float* x     = (const float*)d_in[0];
    const float* tm_w  = (const float*)d_in[1];
    const float* tm_b  = (const float*)d_in[2];
    const float* dc_w  = (const float*)d_in[3];
    const float* gamma = (const float*)d_in[4];
    const float* beta  = (const float*)d_in[5];
    float* out = (float*)d_out;

    k_transpose<<<dim3(HW_/256, B_*G_), 256>>>(x);
    k_fused<<<dim3(H_, G_, B_), 256>>>(tm_w, tm_b, dc_w);
    k_stats<<<C_, 1024>>>();
    k_final<<<B_*C_*HW_/4/1024, 512>>>(x, gamma, beta, out);
}